// round 16
// baseline (speedup 1.0000x reference)
#include <cuda_runtime.h>
#include <cuda_fp16.h>
#include <cstdint>
#include <math.h>

// EulerRosenbrockModel: B=512, D=256, HID=1024, H_STEP=0.01
// out = v + 1.5 B v = W2 (T + 1.5c3 * P) + b2,   P = g .* (W1 vhat)
//   vhat: plain fp16 (error 5e-4 * 2.3e-3 correction weight ~ 1e-6 on out)
//   correction merged into Ts panel's LO half: lo += 2048*1.5c3*P
// 6 launches: split | L1(T, split) | vhat(plain, full-K) | L2(+merge into lo) |
//             S_final(split, z-partials) | reduce_out.

static constexpr int BATCH = 512;
static constexpr int DIM   = 256;
static constexpr int HID   = 1024;
static constexpr int BD    = BATCH * DIM;
static constexpr float LO_SCALE = 2048.0f;
static constexpr float MERGE_SC = 2048.0f * 1.5f * (0.01f / 3.0f);   // 10.24

__device__ float g_T   [BATCH * HID];
__device__ float g_part[4 * BD];
__device__ __half g_ys [BATCH * 2 * DIM];
__device__ __half g_W1s[HID   * 2 * DIM];
__device__ __half g_W2s[DIM   * 2 * HID];
__device__ __half g_Ts [BATCH * 2 * HID];
__device__ __half g_Vp [BD];

// ---------------- low-level helpers ----------------
__device__ __forceinline__ uint32_t smem_u32(const void* p) {
    uint32_t a;
    asm("{ .reg .u64 t; cvta.to.shared.u64 t, %1; cvt.u32.u64 %0, t; }"
        : "=r"(a) : "l"(p));
    return a;
}
__device__ __forceinline__ void cp16(uint32_t dst, const void* src) {
    asm volatile("cp.async.cg.shared.global [%0], [%1], 16;" :: "r"(dst), "l"(src));
}
__device__ __forceinline__ void cp_commit() {
    asm volatile("cp.async.commit_group;" ::: "memory");
}
template<int N>
__device__ __forceinline__ void cp_wait() {
    asm volatile("cp.async.wait_group %0;" :: "n"(N) : "memory");
}
__device__ __forceinline__ void ldm4(uint32_t* r, uint32_t addr) {
    asm volatile("ldmatrix.sync.aligned.m8n8.x4.shared.b16 {%0,%1,%2,%3}, [%4];"
        : "=r"(r[0]), "=r"(r[1]), "=r"(r[2]), "=r"(r[3]) : "r"(addr));
}
__device__ __forceinline__ void ldm2(uint32_t* r, uint32_t addr) {
    asm volatile("ldmatrix.sync.aligned.m8n8.x2.shared.b16 {%0,%1}, [%2];"
        : "=r"(r[0]), "=r"(r[1]) : "r"(addr));
}
__device__ __forceinline__ void mma_f32(float* d, const uint32_t* a, const uint32_t* b) {
    asm volatile("mma.sync.aligned.m16n8k16.row.col.f32.f16.f16.f32 "
        "{%0,%1,%2,%3}, {%4,%5,%6,%7}, {%8,%9}, {%0,%1,%2,%3};"
        : "+f"(d[0]), "+f"(d[1]), "+f"(d[2]), "+f"(d[3])
        : "r"(a[0]), "r"(a[1]), "r"(a[2]), "r"(a[3]), "r"(b[0]), "r"(b[1]));
}
__device__ __forceinline__ void mma_h(uint32_t* d, const uint32_t* a, const uint32_t* b) {
    asm volatile("mma.sync.aligned.m16n8k16.row.col.f16.f16.f16.f16 "
        "{%0,%1}, {%2,%3,%4,%5}, {%6,%7}, {%0,%1};"
        : "+r"(d[0]), "+r"(d[1])
        : "r"(a[0]), "r"(a[1]), "r"(a[2]), "r"(a[3]), "r"(b[0]), "r"(b[1]));
}
__device__ __forceinline__ void st_split(__half* Cs, int Kw, int m, int n,
                                         float v0, float v1) {
    __half2 h = __floats2half2_rn(v0, v1);
    float l0 = (v0 - __half2float(h.x)) * LO_SCALE;
    float l1 = (v1 - __half2float(h.y)) * LO_SCALE;
    __half2 l = __floats2half2_rn(l0, l1);
    *(__half2*)&Cs[(size_t)m * (2 * Kw) + n]      = h;
    *(__half2*)&Cs[(size_t)m * (2 * Kw) + Kw + n] = l;
}

#define MODE_TANH 0   // C fp32 = tanh(acc+bias); Cs = split(result)
#define MODE_MULS 1   // merge: Cs_lo[m][n] += MERGE_SC * acc * (1-T^2)
#define MODE_PART 2   // C fp32 partial at z offset

// CTA tile 32x64, 8 warps, 4-stage cp.async ring, one sync per chunk.
// NREG=3: c0-3 hi*hi (f32 acc), c4-7 hi*lo (f16 acc), c8-11 lo*hi (f32 acc2).
// NREG=1: plain fp16 (hi halves), 4 chunks, f16 acc.
template<int MODE, int NREG>
__global__ void __launch_bounds__(256)
mmagemm(const __half* __restrict__ A, int lda,
        const __half* __restrict__ Bw, int ldb, int Ka,
        float* __restrict__ C, __half* __restrict__ Cs,
        int Nglob, const float* __restrict__ bias, const float* __restrict__ tanhT)
{
    constexpr int CHUNKS = 4 * NREG;
    constexpr int STAGE  = 12288;
    __shared__ __align__(1024) char smem[4 * STAGE];
    const uint32_t sb = smem_u32(smem);

    const int tid = threadIdx.x;
    const int wid = tid >> 5;
    const int lid = tid & 31;
    const int wm  = wid >> 2;
    const int wn  = wid & 3;
    const int m0  = blockIdx.y * 32;
    const int n0  = blockIdx.x * 64;
    const int zoff = blockIdx.z * 256;

    float acc [2][4];
    float acc2[2][4];
    uint32_t acch[2][2];
    #pragma unroll
    for (int g = 0; g < 2; g++) {
        #pragma unroll
        for (int q = 0; q < 4; q++) { acc[g][q] = 0.0f; acc2[g][q] = 0.0f; }
        acch[g][0] = 0u; acch[g][1] = 0u;
    }

    const int m_l = wm * 16 + ((lid >> 3) & 1) * 8 + (lid & 7);
    const int n_l = wn * 16 + (lid >> 4) * 8 + (lid & 7);
    const int a_so = (lid >> 4);
    const int b_so = ((lid >> 3) & 1);
    const uint32_t ax = (uint32_t)((m_l & 7) << 4);
    const uint32_t bx = (uint32_t)((n_l & 7) << 4);

    auto issue = [&](int cc, int st) {
        const int r  = (NREG == 3) ? (cc >> 2) : 0;
        const int kb = (cc & 3) * 64;
        const int ak = zoff + kb + (r == 2 ? Ka : 0);
        const int bk = zoff + kb + (r == 1 ? Ka : 0);
        const uint32_t ab = sb + st * STAGE;
        const uint32_t bb = ab + 4096;
        #pragma unroll
        for (int t = tid; t < 768; t += 256) {
            const int row = (t & 255) >> 3, seg = t & 7;
            const uint32_t sw = (uint32_t)(seg * 16) ^ (uint32_t)((row & 7) << 4);
            if (t < 256) {
                cp16(ab + row * 128 + sw,
                     A + (size_t)(m0 + row) * lda + ak + seg * 8);
            } else {
                const int rr = t >= 512 ? row + 32 : row;
                cp16(bb + rr * 128 + sw,
                     Bw + (size_t)(n0 + rr) * ldb + bk + seg * 8);
            }
        }
    };

    issue(0, 0); cp_commit();
    issue(1, 1); cp_commit();
    if (CHUNKS > 2) { issue(2, 2); cp_commit(); }

    #pragma unroll 1
    for (int c = 0; c < CHUNKS; c++) {
        const int rem = CHUNKS - 1 - c;
        if (rem >= 2)      cp_wait<2>();
        else if (rem == 1) cp_wait<1>();
        else               cp_wait<0>();
        __syncthreads();
        if (c + 3 < CHUNKS) { issue(c + 3, (c + 3) & 3); cp_commit(); }

        const uint32_t ab = sb + (c & 3) * STAGE;
        const uint32_t aRow = ab + m_l * 128;
        const uint32_t bRow = ab + 4096 + n_l * 128;
        if (NREG == 3 && c < 4) {
            #pragma unroll
            for (int k = 0; k < 4; k++) {
                uint32_t a0[4], b[4];
                const uint32_t as = (uint32_t)((k * 2 + a_so) * 16) ^ ax;
                const uint32_t bs = (uint32_t)((k * 2 + b_so) * 16) ^ bx;
                ldm4(a0, aRow + as);
                ldm4(b,  bRow + bs);
                mma_f32(acc[0], a0, b);
                mma_f32(acc[1], a0, b + 2);
            }
        } else if (NREG == 3 && c >= 8) {
            #pragma unroll
            for (int k = 0; k < 4; k++) {
                uint32_t a0[4], b[4];
                const uint32_t as = (uint32_t)((k * 2 + a_so) * 16) ^ ax;
                const uint32_t bs = (uint32_t)((k * 2 + b_so) * 16) ^ bx;
                ldm4(a0, aRow + as);
                ldm4(b,  bRow + bs);
                mma_f32(acc2[0], a0, b);
                mma_f32(acc2[1], a0, b + 2);
            }
        } else {
            #pragma unroll
            for (int k = 0; k < 4; k++) {
                uint32_t a0[4], b[4];
                const uint32_t as = (uint32_t)((k * 2 + a_so) * 16) ^ ax;
                const uint32_t bs = (uint32_t)((k * 2 + b_so) * 16) ^ bx;
                ldm4(a0, aRow + as);
                ldm4(b,  bRow + bs);
                mma_h(acch[0], a0, b);
                mma_h(acch[1], a0, b + 2);
            }
        }
    }

    // combine: NREG==3 -> acc + (acch + acc2)/2048 ; NREG==1 -> acch
    const float cs = (NREG == 3) ? (1.0f / LO_SCALE) : 1.0f;
    #pragma unroll
    for (int g = 0; g < 2; g++) {
        __half2 h0 = *(__half2*)&acch[g][0];
        __half2 h1 = *(__half2*)&acch[g][1];
        acc[g][0] += (__half2float(h0.x) + acc2[g][0]) * cs;
        acc[g][1] += (__half2float(h0.y) + acc2[g][1]) * cs;
        acc[g][2] += (__half2float(h1.x) + acc2[g][2]) * cs;
        acc[g][3] += (__half2float(h1.y) + acc2[g][3]) * cs;
    }

    const int gid  = lid >> 2;
    const int tid4 = lid & 3;
    #pragma unroll
    for (int g = 0; g < 2; g++) {
        const int m = m0 + wm * 16 + gid;
        const int n = n0 + wn * 16 + g * 8 + tid4 * 2;
        const float* ac = acc[g];
        if (MODE == MODE_TANH) {
            const float b0v = bias[n], b1v = bias[n + 1];
            float v00 = tanhf(ac[0] + b0v), v01 = tanhf(ac[1] + b1v);
            float v10 = tanhf(ac[2] + b0v), v11 = tanhf(ac[3] + b1v);
            *(float2*)&C[(size_t)m * Nglob + n]       = make_float2(v00, v01);
            *(float2*)&C[(size_t)(m + 8) * Nglob + n] = make_float2(v10, v11);
            st_split(Cs, Nglob, m,     n, v00, v01);
            st_split(Cs, Nglob, m + 8, n, v10, v11);
        } else if (MODE == MODE_MULS) {
            // merge correction into lo half of the split panel Cs (Kw = Nglob)
            float2 t0 = *(const float2*)&tanhT[(size_t)m * Nglob + n];
            float2 t1 = *(const float2*)&tanhT[(size_t)(m + 8) * Nglob + n];
            float p00 = MERGE_SC * ac[0] * (1.0f - t0.x * t0.x);
            float p01 = MERGE_SC * ac[1] * (1.0f - t0.y * t0.y);
            float p10 = MERGE_SC * ac[2] * (1.0f - t1.x * t1.x);
            float p11 = MERGE_SC * ac[3] * (1.0f - t1.y * t1.y);
            __half* lo0 = &Cs[(size_t)m * (2 * Nglob) + Nglob + n];
            __half* lo1 = &Cs[(size_t)(m + 8) * (2 * Nglob) + Nglob + n];
            __half2 o0 = *(__half2*)lo0;
            __half2 o1 = *(__half2*)lo1;
            *(__half2*)lo0 = __floats2half2_rn(__half2float(o0.x) + p00,
                                               __half2float(o0.y) + p01);
            *(__half2*)lo1 = __floats2half2_rn(__half2float(o1.x) + p10,
                                               __half2float(o1.y) + p11);
        } else {
            float* Cb = C + (size_t)blockIdx.z * BD;
            *(float2*)&Cb[(size_t)m * Nglob + n]       = make_float2(ac[0], ac[1]);
            *(float2*)&Cb[(size_t)(m + 8) * Nglob + n] = make_float2(ac[2], ac[3]);
        }
    }
}

// ---- vhat: 512x256, K=1024 plain fp16 (hi halves), f16-acc, full K.
// CTA tile 32x32, grid (8,16)=128 CTAs. Epilogue: Vp = fp16(acc + b2[n]).
__global__ void __launch_bounds__(256)
sgemm_vhat(const __half* __restrict__ A, int lda,
           const __half* __restrict__ Bw, int ldb,
           const float* __restrict__ bias, __half* __restrict__ outH)
{
    constexpr int CHUNKS = 16;
    constexpr int STAGE  = 8192;
    __shared__ __align__(1024) char smem[4 * STAGE];
    const uint32_t sb = smem_u32(smem);

    const int tid = threadIdx.x;
    const int wid = tid >> 5;
    const int lid = tid & 31;
    const int wm  = wid >> 2;
    const int wn  = wid & 3;
    const int m0  = blockIdx.y * 32;
    const int n0  = blockIdx.x * 32;

    uint32_t acch[2] = {0u, 0u};

    const int m_l  = wm * 16 + ((lid >> 3) & 1) * 8 + (lid & 7);
    const int a_so = (lid >> 4);
    const int n_l2 = wn * 8 + (lid & 7);
    const int b_sg = (lid >> 3) & 1;
    const uint32_t ax = (uint32_t)((m_l & 7) << 4);
    const uint32_t bx = (uint32_t)((n_l2 & 7) << 4);

    auto issue = [&](int cc, int st) {
        const int kb = cc * 64;
        const uint32_t ab = sb + st * STAGE;
        const uint32_t bb = ab + 4096;
        #pragma unroll
        for (int t = tid; t < 512; t += 256) {
            const int row = (t & 255) >> 3, seg = t & 7;
            const uint32_t sw = (uint32_t)(seg * 16) ^ (uint32_t)((row & 7) << 4);
            if (t < 256)
                cp16(ab + row * 128 + sw,
                     A + (size_t)(m0 + row) * lda + kb + seg * 8);
            else
                cp16(bb + row * 128 + sw,
                     Bw + (size_t)(n0 + row) * ldb + kb + seg * 8);
        }
    };

    issue(0, 0); cp_commit();
    issue(1, 1); cp_commit();
    issue(2, 2); cp_commit();

    #pragma unroll 1
    for (int c = 0; c < CHUNKS; c++) {
        const int rem = CHUNKS - 1 - c;
        if (rem >= 2)      cp_wait<2>();
        else if (rem == 1) cp_wait<1>();
        else               cp_wait<0>();
        __syncthreads();
        if (c + 3 < CHUNKS) { issue(c + 3, (c + 3) & 3); cp_commit(); }

        const uint32_t ab = sb + (c & 3) * STAGE;
        const uint32_t aRow = ab + m_l * 128;
        const uint32_t bRow = ab + 4096 + n_l2 * 128;
        #pragma unroll
        for (int k = 0; k < 4; k++) {
            uint32_t a0[4], b[2];
            const uint32_t as = (uint32_t)((k * 2 + a_so) * 16) ^ ax;
            const uint32_t bs = (uint32_t)((k * 2 + b_sg) * 16) ^ bx;
            ldm4(a0, aRow + as);
            ldm2(b,  bRow + bs);
            mma_h(acch, a0, b);
        }
    }

    const int gid  = lid >> 2;
    const int tid4 = lid & 3;
    const int m = m0 + wm * 16 + gid;
    const int n = n0 + wn * 8 + tid4 * 2;
    __half2 h0 = *(__half2*)&acch[0];
    __half2 h1 = *(__half2*)&acch[1];
    const float b0v = bias[n], b1v = bias[n + 1];
    *(__half2*)&outH[(size_t)m * DIM + n] =
        __floats2half2_rn(__half2float(h0.x) + b0v, __half2float(h0.y) + b1v);
    *(__half2*)&outH[(size_t)(m + 8) * DIM + n] =
        __floats2half2_rn(__half2float(h1.x) + b0v, __half2float(h1.y) + b1v);
}

// fused split of y, W1, W2 -> fp16 [hi | 2048*lo] panels (one launch)
__global__ void __launch_bounds__(256)
split_all(const float* __restrict__ y, const float* __restrict__ W1,
          const float* __restrict__ W2,
          __half* __restrict__ ys, __half* __restrict__ W1s,
          __half* __restrict__ W2s)
{
    int b = blockIdx.x;
    const float* in;
    __half* outs;
    int K;
    if (b < 128)      { in = y;  outs = ys;  K = DIM; }
    else if (b < 384) { in = W1; outs = W1s; K = DIM;  b -= 128; }
    else              { in = W2; outs = W2s; K = HID;  b -= 384; }

    const int e4 = (b * 256 + threadIdx.x) * 4;
    const int row = e4 / K, k = e4 % K;
    float4 v = *(const float4*)&in[e4];
    __half2 h0 = __floats2half2_rn(v.x, v.y);
    __half2 h1 = __floats2half2_rn(v.z, v.w);
    __half2 l0 = __floats2half2_rn((v.x - __half2float(h0.x)) * LO_SCALE,
                                   (v.y - __half2float(h0.y)) * LO_SCALE);
    __half2 l1 = __floats2half2_rn((v.z - __half2float(h1.x)) * LO_SCALE,
                                   (v.w - __half2float(h1.y)) * LO_SCALE);
    *(__half2*)&outs[(size_t)row * 2 * K + k]         = h0;
    *(__half2*)&outs[(size_t)row * 2 * K + k + 2]     = h1;
    *(__half2*)&outs[(size_t)row * 2 * K + K + k]     = l0;
    *(__half2*)&outs[(size_t)row * 2 * K + K + k + 2] = l1;
}

// out fp32 = sum(partials) + b2
__global__ void __launch_bounds__(256)
reduce_out(const float* __restrict__ part, const float* __restrict__ bias,
           float* __restrict__ out)
{
    const int e4 = (blockIdx.x * 256 + threadIdx.x) * 4;
    float4 s0 = *(const float4*)&part[e4];
    float4 s1 = *(const float4*)&part[BD     + e4];
    float4 s2 = *(const float4*)&part[BD * 2 + e4];
    float4 s3 = *(const float4*)&part[BD * 3 + e4];
    float4 b  = *(const float4*)&bias[e4 & (DIM - 1)];
    float4 r;
    r.x = (s0.x + s1.x) + (s2.x + s3.x) + b.x;
    r.y = (s0.y + s1.y) + (s2.y + s3.y) + b.y;
    r.z = (s0.z + s1.z) + (s2.z + s3.z) + b.z;
    r.w = (s0.w + s1.w) + (s2.w + s3.w) + b.w;
    *(float4*)&out[e4] = r;
}

extern "C" void kernel_launch(void* const* d_in, const int* in_sizes, int n_in,
                              void* d_out, int out_size)
{
    const float* y  = (const float*)d_in[0];
    const float* W1 = (const float*)d_in[1];
    const float* b1 = (const float*)d_in[2];
    const float* W2 = (const float*)d_in[3];
    const float* b2 = (const float*)d_in[4];
    float* out = (float*)d_out;

    float *pT, *pPart;
    __half *pYs, *pW1s, *pW2s, *pTs, *pVp;
    cudaGetSymbolAddress((void**)&pT,    g_T);
    cudaGetSymbolAddress((void**)&pPart, g_part);
    cudaGetSymbolAddress((void**)&pYs,   g_ys);
    cudaGetSymbolAddress((void**)&pW1s,  g_W1s);
    cudaGetSymbolAddress((void**)&pW2s,  g_W2s);
    cudaGetSymbolAddress((void**)&pTs,   g_Ts);
    cudaGetSymbolAddress((void**)&pVp,   g_Vp);

    dim3 gL(HID / 64, BATCH / 32, 1);   // (16,16,1) = 256 CTAs
    dim3 gS(DIM / 64, BATCH / 32, 4);   // ( 4,16,4) = 256 CTAs
    dim3 gV(DIM / 32, BATCH / 32);      // ( 8,16)   = 128 CTAs
    const int gR = BD / (256 * 4);      // 128

    split_all<<<640, 256>>>(y, W1, W2, pYs, pW1s, pW2s);

    // T = tanh(y W1^T + b1)  (split precision; writes g_T fp32 + g_Ts panel)
    mmagemm<MODE_TANH, 3><<<gL, 256>>>(pYs, 2 * DIM, pW1s, 2 * DIM, DIM,
                                       pT, pTs, HID, b1, nullptr);
    // vhat = fp16( T_hi W2_hi^T + b2 )   (plain, full K, no reduce)
    sgemm_vhat<<<gV, 256>>>(pTs, 2 * HID, pW2s, 2 * HID, b2, pVp);

    // Ts_lo += 10.24 * (1-T^2) .* (vhat W1_hi^T)   (merge correction into lo)
    mmagemm<MODE_MULS, 1><<<gL, 256>>>(pVp, DIM, pW1s, 2 * DIM, 0,
                                       nullptr, pTs, HID, nullptr, pT);

    // out = W2 (T + 1.5c3 P) + b2 : split GEMM on modified Ts, z-partials
    mmagemm<MODE_PART, 3><<<gS, 256>>>(pTs, 2 * HID, pW2s, 2 * HID, HID,
                                       pPart, nullptr, DIM, nullptr, nullptr);
    reduce_out<<<gR, 256>>>(pPart, b2, out);
}

// round 17
// speedup vs baseline: 1.1146x; 1.1146x over previous
#include <cuda_runtime.h>
#include <cuda_fp16.h>
#include <cstdint>
#include <math.h>

// EulerRosenbrockModel: B=512, D=256, HID=1024, H_STEP=0.01
// out = v + 1.5 B v,  B = (h/3) J   (dropped 1.5 B^2 v ~ 8e-6 rel)
// fp16 double-split (hi + 2048*lo): hi*hi f32-acc, cross f16-acc (/2048).
// 5 launches: split | L1(T, split) | S1(split -> z-partials) |
//             L2'(v-reduce fused into prologue, corr -> Pp) |
//             S2'(full-K plain, epilogue v-reduce + AXPY -> out).

static constexpr int BATCH = 512;
static constexpr int DIM   = 256;
static constexpr int HID   = 1024;
static constexpr int BD    = BATCH * DIM;
static constexpr float LO_SCALE = 2048.0f;

__device__ float g_T   [BATCH * HID];
__device__ float g_part[4 * BD];
__device__ __half g_ys [BATCH * 2 * DIM];
__device__ __half g_W1s[HID   * 2 * DIM];
__device__ __half g_W2s[DIM   * 2 * HID];
__device__ __half g_Ts [BATCH * 2 * HID];
__device__ __half g_Pp [BATCH * HID];

// ---------------- low-level helpers ----------------
__device__ __forceinline__ uint32_t smem_u32(const void* p) {
    uint32_t a;
    asm("{ .reg .u64 t; cvta.to.shared.u64 t, %1; cvt.u32.u64 %0, t; }"
        : "=r"(a) : "l"(p));
    return a;
}
__device__ __forceinline__ void cp16(uint32_t dst, const void* src) {
    asm volatile("cp.async.cg.shared.global [%0], [%1], 16;" :: "r"(dst), "l"(src));
}
__device__ __forceinline__ void cp_commit() {
    asm volatile("cp.async.commit_group;" ::: "memory");
}
template<int N>
__device__ __forceinline__ void cp_wait() {
    asm volatile("cp.async.wait_group %0;" :: "n"(N) : "memory");
}
__device__ __forceinline__ void ldm4(uint32_t* r, uint32_t addr) {
    asm volatile("ldmatrix.sync.aligned.m8n8.x4.shared.b16 {%0,%1,%2,%3}, [%4];"
        : "=r"(r[0]), "=r"(r[1]), "=r"(r[2]), "=r"(r[3]) : "r"(addr));
}
__device__ __forceinline__ void ldm2(uint32_t* r, uint32_t addr) {
    asm volatile("ldmatrix.sync.aligned.m8n8.x2.shared.b16 {%0,%1}, [%2];"
        : "=r"(r[0]), "=r"(r[1]) : "r"(addr));
}
__device__ __forceinline__ void mma_f32(float* d, const uint32_t* a, const uint32_t* b) {
    asm volatile("mma.sync.aligned.m16n8k16.row.col.f32.f16.f16.f32 "
        "{%0,%1,%2,%3}, {%4,%5,%6,%7}, {%8,%9}, {%0,%1,%2,%3};"
        : "+f"(d[0]), "+f"(d[1]), "+f"(d[2]), "+f"(d[3])
        : "r"(a[0]), "r"(a[1]), "r"(a[2]), "r"(a[3]), "r"(b[0]), "r"(b[1]));
}
__device__ __forceinline__ void mma_h(uint32_t* d, const uint32_t* a, const uint32_t* b) {
    asm volatile("mma.sync.aligned.m16n8k16.row.col.f16.f16.f16.f16 "
        "{%0,%1}, {%2,%3,%4,%5}, {%6,%7}, {%0,%1};"
        : "+r"(d[0]), "+r"(d[1])
        : "r"(a[0]), "r"(a[1]), "r"(a[2]), "r"(a[3]), "r"(b[0]), "r"(b[1]));
}
__device__ __forceinline__ void st_split(__half* Cs, int Kw, int m, int n,
                                         float v0, float v1) {
    __half2 h = __floats2half2_rn(v0, v1);
    float l0 = (v0 - __half2float(h.x)) * LO_SCALE;
    float l1 = (v1 - __half2float(h.y)) * LO_SCALE;
    __half2 l = __floats2half2_rn(l0, l1);
    *(__half2*)&Cs[(size_t)m * (2 * Kw) + n]      = h;
    *(__half2*)&Cs[(size_t)m * (2 * Kw) + Kw + n] = l;
}

#define MODE_TANH 0
#define MODE_PART 2

// CTA tile 32x64, 8 warps, 4-stage cp.async ring, one sync per chunk.
// NREG=3 split precision: chunks 0-3 hi*hi (f32), 4-11 cross (f16, /2048).
template<int MODE, int NREG>
__global__ void __launch_bounds__(256)
mmagemm(const __half* __restrict__ A, int lda,
        const __half* __restrict__ Bw, int ldb, int Ka,
        float* __restrict__ C, __half* __restrict__ Cs,
        int Nglob, const float* __restrict__ bias)
{
    constexpr int CHUNKS = 4 * NREG;
    constexpr int STAGE  = 12288;
    __shared__ __align__(1024) char smem[4 * STAGE];
    const uint32_t sb = smem_u32(smem);

    const int tid = threadIdx.x;
    const int wid = tid >> 5;
    const int lid = tid & 31;
    const int wm  = wid >> 2;
    const int wn  = wid & 3;
    const int m0  = blockIdx.y * 32;
    const int n0  = blockIdx.x * 64;
    const int zoff = blockIdx.z * 256;

    float acc[2][4];
    uint32_t acch[2][2];
    #pragma unroll
    for (int g = 0; g < 2; g++) {
        #pragma unroll
        for (int q = 0; q < 4; q++) acc[g][q] = 0.0f;
        acch[g][0] = 0u; acch[g][1] = 0u;
    }

    const int m_l = wm * 16 + ((lid >> 3) & 1) * 8 + (lid & 7);
    const int n_l = wn * 16 + (lid >> 4) * 8 + (lid & 7);
    const int a_so = (lid >> 4);
    const int b_so = ((lid >> 3) & 1);
    const uint32_t ax = (uint32_t)((m_l & 7) << 4);
    const uint32_t bx = (uint32_t)((n_l & 7) << 4);

    auto issue = [&](int cc, int st) {
        const int r  = cc >> 2;
        const int kb = (cc & 3) * 64;
        const int ak = zoff + kb + (r == 2 ? Ka : 0);
        const int bk = zoff + kb + (r == 1 ? Ka : 0);
        const uint32_t ab = sb + st * STAGE;
        const uint32_t bb = ab + 4096;
        #pragma unroll
        for (int t = tid; t < 768; t += 256) {
            const int row = (t & 255) >> 3, seg = t & 7;
            const uint32_t sw = (uint32_t)(seg * 16) ^ (uint32_t)((row & 7) << 4);
            if (t < 256) {
                cp16(ab + row * 128 + sw,
                     A + (size_t)(m0 + row) * lda + ak + seg * 8);
            } else {
                const int rr = t >= 512 ? row + 32 : row;
                cp16(bb + rr * 128 + sw,
                     Bw + (size_t)(n0 + rr) * ldb + bk + seg * 8);
            }
        }
    };

    issue(0, 0); cp_commit();
    issue(1, 1); cp_commit();
    issue(2, 2); cp_commit();

    #pragma unroll 1
    for (int c = 0; c < CHUNKS; c++) {
        const int rem = CHUNKS - 1 - c;
        if (rem >= 2)      cp_wait<2>();
        else if (rem == 1) cp_wait<1>();
        else               cp_wait<0>();
        __syncthreads();
        if (c + 3 < CHUNKS) { issue(c + 3, (c + 3) & 3); cp_commit(); }

        const uint32_t ab = sb + (c & 3) * STAGE;
        const uint32_t aRow = ab + m_l * 128;
        const uint32_t bRow = ab + 4096 + n_l * 128;
        if (c < 4) {
            #pragma unroll
            for (int k = 0; k < 4; k++) {
                uint32_t a0[4], b[4];
                const uint32_t as = (uint32_t)((k * 2 + a_so) * 16) ^ ax;
                const uint32_t bs = (uint32_t)((k * 2 + b_so) * 16) ^ bx;
                ldm4(a0, aRow + as);
                ldm4(b,  bRow + bs);
                mma_f32(acc[0], a0, b);
                mma_f32(acc[1], a0, b + 2);
            }
        } else {
            #pragma unroll
            for (int k = 0; k < 4; k++) {
                uint32_t a0[4], b[4];
                const uint32_t as = (uint32_t)((k * 2 + a_so) * 16) ^ ax;
                const uint32_t bs = (uint32_t)((k * 2 + b_so) * 16) ^ bx;
                ldm4(a0, aRow + as);
                ldm4(b,  bRow + bs);
                mma_h(acch[0], a0, b);
                mma_h(acch[1], a0, b + 2);
            }
        }
    }

    #pragma unroll
    for (int g = 0; g < 2; g++) {
        __half2 h0 = *(__half2*)&acch[g][0];
        __half2 h1 = *(__half2*)&acch[g][1];
        acc[g][0] += __half2float(h0.x) * (1.0f / LO_SCALE);
        acc[g][1] += __half2float(h0.y) * (1.0f / LO_SCALE);
        acc[g][2] += __half2float(h1.x) * (1.0f / LO_SCALE);
        acc[g][3] += __half2float(h1.y) * (1.0f / LO_SCALE);
    }

    const int gid  = lid >> 2;
    const int tid4 = lid & 3;
    #pragma unroll
    for (int g = 0; g < 2; g++) {
        const int m = m0 + wm * 16 + gid;
        const int n = n0 + wn * 16 + g * 8 + tid4 * 2;
        const float* ac = acc[g];
        if (MODE == MODE_TANH) {
            const float b0v = bias[n], b1v = bias[n + 1];
            float v00 = tanhf(ac[0] + b0v), v01 = tanhf(ac[1] + b1v);
            float v10 = tanhf(ac[2] + b0v), v11 = tanhf(ac[3] + b1v);
            *(float2*)&C[(size_t)m * Nglob + n]       = make_float2(v00, v01);
            *(float2*)&C[(size_t)(m + 8) * Nglob + n] = make_float2(v10, v11);
            st_split(Cs, Nglob, m,     n, v00, v01);
            st_split(Cs, Nglob, m + 8, n, v10, v11);
        } else {
            float* Cb = C + (size_t)blockIdx.z * BD;
            *(float2*)&Cb[(size_t)m * Nglob + n]       = make_float2(ac[0], ac[1]);
            *(float2*)&Cb[(size_t)(m + 8) * Nglob + n] = make_float2(ac[2], ac[3]);
        }
    }
}

// ---- L2': correction GEMM with fused v-reduce.
// Pp[512,HID] = fp16( (Vp W1_hi^T) .* (1 - T^2) ),  Vp built in-CTA from
// S1 partials + b2 and staged in smem in the chunk-swizzled A layout.
// CTA tile 32x64, grid (16,16). A static (16KB), B 4-stage ring (8KB/stage).
__global__ void __launch_bounds__(256)
lgemm_corr(const float* __restrict__ part, const float* __restrict__ b2,
           const __half* __restrict__ W1s, const float* __restrict__ tanhT,
           __half* __restrict__ Pp)
{
    __shared__ __align__(1024) char smem[16384 + 32768];
    const uint32_t sbA = smem_u32(smem);
    const uint32_t sbB = sbA + 16384;

    const int tid = threadIdx.x;
    const int wid = tid >> 5;
    const int lid = tid & 31;
    const int wm  = wid >> 2;
    const int wn  = wid & 3;
    const int m0  = blockIdx.y * 32;
    const int n0  = blockIdx.x * 64;
    const int ldb = 2 * DIM;

    // ---- prologue: A = fp16(v) in chunk-swizzled layout ----
    #pragma unroll
    for (int u = tid; u < 1024; u += 256) {
        const int row = u >> 5;          // 0..31
        const int sg  = u & 31;          // global seg (8 cols each)
        const int cb  = sg * 8;
        const float* p = part + (size_t)(m0 + row) * DIM + cb;
        float4 s0a = *(const float4*)(p);
        float4 s0b = *(const float4*)(p + 4);
        float4 s1a = *(const float4*)(p + BD);
        float4 s1b = *(const float4*)(p + BD + 4);
        float4 s2a = *(const float4*)(p + 2 * BD);
        float4 s2b = *(const float4*)(p + 2 * BD + 4);
        float4 s3a = *(const float4*)(p + 3 * BD);
        float4 s3b = *(const float4*)(p + 3 * BD + 4);
        float4 ba  = *(const float4*)&b2[cb];
        float4 bb  = *(const float4*)&b2[cb + 4];
        float v0 = (s0a.x + s1a.x) + (s2a.x + s3a.x) + ba.x;
        float v1 = (s0a.y + s1a.y) + (s2a.y + s3a.y) + ba.y;
        float v2 = (s0a.z + s1a.z) + (s2a.z + s3a.z) + ba.z;
        float v3 = (s0a.w + s1a.w) + (s2a.w + s3a.w) + ba.w;
        float v4 = (s0b.x + s1b.x) + (s2b.x + s3b.x) + bb.x;
        float v5 = (s0b.y + s1b.y) + (s2b.y + s3b.y) + bb.y;
        float v6 = (s0b.z + s1b.z) + (s2b.z + s3b.z) + bb.z;
        float v7 = (s0b.w + s1b.w) + (s2b.w + s3b.w) + bb.w;
        uint4 pk;
        __half2 h01 = __floats2half2_rn(v0, v1);
        __half2 h23 = __floats2half2_rn(v2, v3);
        __half2 h45 = __floats2half2_rn(v4, v5);
        __half2 h67 = __floats2half2_rn(v6, v7);
        pk.x = *(uint32_t*)&h01; pk.y = *(uint32_t*)&h23;
        pk.z = *(uint32_t*)&h45; pk.w = *(uint32_t*)&h67;
        const int chunk = sg >> 3, seg = sg & 7;
        const uint32_t addr = sbA + chunk * 4096 + row * 128 +
                              (((uint32_t)(seg * 16)) ^ ((uint32_t)((row & 7) << 4)));
        asm volatile("st.shared.v4.b32 [%0], {%1,%2,%3,%4};"
            :: "r"(addr), "r"(pk.x), "r"(pk.y), "r"(pk.z), "r"(pk.w) : "memory");
    }

    uint32_t acch[2][2] = {{0u, 0u}, {0u, 0u}};

    const int m_l = wm * 16 + ((lid >> 3) & 1) * 8 + (lid & 7);
    const int n_l = wn * 16 + (lid >> 4) * 8 + (lid & 7);
    const int a_so = (lid >> 4);
    const int b_so = ((lid >> 3) & 1);
    const uint32_t ax = (uint32_t)((m_l & 7) << 4);
    const uint32_t bx = (uint32_t)((n_l & 7) << 4);

    auto issueB = [&](int cc, int st) {
        const int kb = cc * 64;
        const uint32_t bb = sbB + st * 8192;
        #pragma unroll
        for (int t = tid; t < 512; t += 256) {
            const int row = t >> 3, seg = t & 7;
            const uint32_t sw = (uint32_t)(seg * 16) ^ (uint32_t)((row & 7) << 4);
            cp16(bb + row * 128 + sw,
                 W1s + (size_t)(n0 + row) * ldb + kb + seg * 8);
        }
    };

    issueB(0, 0); cp_commit();
    issueB(1, 1); cp_commit();
    issueB(2, 2); cp_commit();

    #pragma unroll 1
    for (int c = 0; c < 4; c++) {
        const int rem = 3 - c;
        if (rem >= 2)      cp_wait<2>();
        else if (rem == 1) cp_wait<1>();
        else               cp_wait<0>();
        __syncthreads();            // also orders the prologue A stores (c==0)
        if (c + 3 < 4) { issueB(c + 3, (c + 3) & 3); cp_commit(); }

        const uint32_t aRow = sbA + c * 4096 + m_l * 128;
        const uint32_t bRow = sbB + (c & 3) * 8192 + n_l * 128;
        #pragma unroll
        for (int k = 0; k < 4; k++) {
            uint32_t a0[4], b[4];
            const uint32_t as = (uint32_t)((k * 2 + a_so) * 16) ^ ax;
            const uint32_t bs = (uint32_t)((k * 2 + b_so) * 16) ^ bx;
            ldm4(a0, aRow + as);
            ldm4(b,  bRow + bs);
            mma_h(acch[0], a0, b);
            mma_h(acch[1], a0, b + 2);
        }
    }

    const int gid  = lid >> 2;
    const int tid4 = lid & 3;
    #pragma unroll
    for (int g = 0; g < 2; g++) {
        const int m = m0 + wm * 16 + gid;
        const int n = n0 + wn * 16 + g * 8 + tid4 * 2;
        __half2 h0 = *(__half2*)&acch[g][0];
        __half2 h1 = *(__half2*)&acch[g][1];
        float2 t0 = *(const float2*)&tanhT[(size_t)m * HID + n];
        float2 t1 = *(const float2*)&tanhT[(size_t)(m + 8) * HID + n];
        __half2 o0 = __floats2half2_rn(
            __half2float(h0.x) * (1.0f - t0.x * t0.x),
            __half2float(h0.y) * (1.0f - t0.y * t0.y));
        __half2 o1 = __floats2half2_rn(
            __half2float(h1.x) * (1.0f - t1.x * t1.x),
            __half2float(h1.y) * (1.0f - t1.y * t1.y));
        *(__half2*)&Pp[(size_t)m * HID + n]       = o0;
        *(__half2*)&Pp[(size_t)(m + 8) * HID + n] = o1;
    }
}

// ---- S2': 512x256, K=1024 plain fp16 full-K, f16-acc.
// Epilogue: out = ((p0+p1)+(p2+p3)) + b2[n] + scale*acc   (v fused in).
__global__ void __launch_bounds__(256)
sgemm_out(const __half* __restrict__ A, int lda,
          const __half* __restrict__ Bw, int ldb,
          const float* __restrict__ part, const float* __restrict__ b2,
          float scale, float* __restrict__ outF)
{
    constexpr int CHUNKS = 16;
    constexpr int STAGE  = 8192;
    __shared__ __align__(1024) char smem[4 * STAGE];
    const uint32_t sb = smem_u32(smem);

    const int tid = threadIdx.x;
    const int wid = tid >> 5;
    const int lid = tid & 31;
    const int wm  = wid >> 2;
    const int wn  = wid & 3;
    const int m0  = blockIdx.y * 32;
    const int n0  = blockIdx.x * 32;

    uint32_t acch[2] = {0u, 0u};

    const int m_l  = wm * 16 + ((lid >> 3) & 1) * 8 + (lid & 7);
    const int a_so = (lid >> 4);
    const int n_l2 = wn * 8 + (lid & 7);
    const int b_sg = (lid >> 3) & 1;
    const uint32_t ax = (uint32_t)((m_l & 7) << 4);
    const uint32_t bx = (uint32_t)((n_l2 & 7) << 4);

    auto issue = [&](int cc, int st) {
        const int kb = cc * 64;
        const uint32_t ab = sb + st * STAGE;
        const uint32_t bb = ab + 4096;
        #pragma unroll
        for (int t = tid; t < 512; t += 256) {
            const int row = (t & 255) >> 3, seg = t & 7;
            const uint32_t sw = (uint32_t)(seg * 16) ^ (uint32_t)((row & 7) << 4);
            if (t < 256)
                cp16(ab + row * 128 + sw,
                     A + (size_t)(m0 + row) * lda + kb + seg * 8);
            else
                cp16(bb + row * 128 + sw,
                     Bw + (size_t)(n0 + row) * ldb + kb + seg * 8);
        }
    };

    issue(0, 0); cp_commit();
    issue(1, 1); cp_commit();
    issue(2, 2); cp_commit();

    #pragma unroll 1
    for (int c = 0; c < CHUNKS; c++) {
        const int rem = CHUNKS - 1 - c;
        if (rem >= 2)      cp_wait<2>();
        else if (rem == 1) cp_wait<1>();
        else               cp_wait<0>();
        __syncthreads();
        if (c + 3 < CHUNKS) { issue(c + 3, (c + 3) & 3); cp_commit(); }

        const uint32_t ab = sb + (c & 3) * STAGE;
        const uint32_t aRow = ab + m_l * 128;
        const uint32_t bRow = ab + 4096 + n_l2 * 128;
        #pragma unroll
        for (int k = 0; k < 4; k++) {
            uint32_t a0[4], b[2];
            const uint32_t as = (uint32_t)((k * 2 + a_so) * 16) ^ ax;
            const uint32_t bs = (uint32_t)((k * 2 + b_sg) * 16) ^ bx;
            ldm4(a0, aRow + as);
            ldm2(b,  bRow + bs);
            mma_h(acch, a0, b);
        }
    }

    const int gid  = lid >> 2;
    const int tid4 = lid & 3;
    const int m = m0 + wm * 16 + gid;
    const int n = n0 + wn * 8 + tid4 * 2;
    __half2 h0 = *(__half2*)&acch[0];
    __half2 h1 = *(__half2*)&acch[1];
    const float2 bv = *(const float2*)&b2[n];
    #pragma unroll
    for (int g = 0; g < 2; g++) {
        const int mm = m + g * 8;
        const size_t off = (size_t)mm * DIM + n;
        float2 p0 = *(const float2*)&part[off];
        float2 p1 = *(const float2*)&part[BD + off];
        float2 p2 = *(const float2*)&part[2 * (size_t)BD + off];
        float2 p3 = *(const float2*)&part[3 * (size_t)BD + off];
        float vx = (p0.x + p1.x) + (p2.x + p3.x) + bv.x;
        float vy = (p0.y + p1.y) + (p2.y + p3.y) + bv.y;
        float ax0 = g == 0 ? __half2float(h0.x) : __half2float(h1.x);
        float ax1 = g == 0 ? __half2float(h0.y) : __half2float(h1.y);
        *(float2*)&outF[off] = make_float2(fmaf(scale, ax0, vx),
                                           fmaf(scale, ax1, vy));
    }
}

// fused split of y, W1, W2 -> fp16 [hi | 2048*lo] panels (one launch)
__global__ void __launch_bounds__(256)
split_all(const float* __restrict__ y, const float* __restrict__ W1,
          const float* __restrict__ W2,
          __half* __restrict__ ys, __half* __restrict__ W1s,
          __half* __restrict__ W2s)
{
    int b = blockIdx.x;
    const float* in;
    __half* outs;
    int K;
    if (b < 128)      { in = y;  outs = ys;  K = DIM; }
    else if (b < 384) { in = W1; outs = W1s; K = DIM;  b -= 128; }
    else              { in = W2; outs = W2s; K = HID;  b -= 384; }

    const int e4 = (b * 256 + threadIdx.x) * 4;
    const int row = e4 / K, k = e4 % K;
    float4 v = *(const float4*)&in[e4];
    __half2 h0 = __floats2half2_rn(v.x, v.y);
    __half2 h1 = __floats2half2_rn(v.z, v.w);
    __half2 l0 = __floats2half2_rn((v.x - __half2float(h0.x)) * LO_SCALE,
                                   (v.y - __half2float(h0.y)) * LO_SCALE);
    __half2 l1 = __floats2half2_rn((v.z - __half2float(h1.x)) * LO_SCALE,
                                   (v.w - __half2float(h1.y)) * LO_SCALE);
    *(__half2*)&outs[(size_t)row * 2 * K + k]         = h0;
    *(__half2*)&outs[(size_t)row * 2 * K + k + 2]     = h1;
    *(__half2*)&outs[(size_t)row * 2 * K + K + k]     = l0;
    *(__half2*)&outs[(size_t)row * 2 * K + K + k + 2] = l1;
}

extern "C" void kernel_launch(void* const* d_in, const int* in_sizes, int n_in,
                              void* d_out, int out_size)
{
    const float* y  = (const float*)d_in[0];
    const float* W1 = (const float*)d_in[1];
    const float* b1 = (const float*)d_in[2];
    const float* W2 = (const float*)d_in[3];
    const float* b2 = (const float*)d_in[4];
    float* out = (float*)d_out;

    float *pT, *pPart;
    __half *pYs, *pW1s, *pW2s, *pTs, *pPp;
    cudaGetSymbolAddress((void**)&pT,    g_T);
    cudaGetSymbolAddress((void**)&pPart, g_part);
    cudaGetSymbolAddress((void**)&pYs,   g_ys);
    cudaGetSymbolAddress((void**)&pW1s,  g_W1s);
    cudaGetSymbolAddress((void**)&pW2s,  g_W2s);
    cudaGetSymbolAddress((void**)&pTs,   g_Ts);
    cudaGetSymbolAddress((void**)&pPp,   g_Pp);

    dim3 gL(HID / 64, BATCH / 32, 1);   // (16,16,1) = 256 CTAs
    dim3 gS(DIM / 64, BATCH / 32, 4);   // ( 4,16,4) = 256 CTAs
    dim3 gO(DIM / 32, BATCH / 32);      // ( 8,16)   = 128 CTAs

    const float c3 = 0.01f / 3.0f;

    split_all<<<640, 256>>>(y, W1, W2, pYs, pW1s, pW2s);

    // T = tanh(y W1^T + b1)   (split precision)
    mmagemm<MODE_TANH, 3><<<gL, 256>>>(pYs, 2 * DIM, pW1s, 2 * DIM, DIM,
                                       pT, pTs, HID, b1);
    // S1: z-partials of T W2^T (split precision)
    mmagemm<MODE_PART, 3><<<gS, 256>>>(pTs, 2 * HID, pW2s, 2 * HID, HID,
                                       pPart, nullptr, DIM, nullptr);
    // L2': Pp = (Vp W1_hi^T) .* (1-T^2), Vp built in-CTA from partials + b2
    lgemm_corr<<<gL, 256>>>(pPart, b2, pW1s, pT, pPp);
    // S2': out = v + 1.5c3 * (Pp W2_hi^T), v re-reduced in epilogue
    sgemm_out<<<gO, 256>>>(pPp, HID, pW2s, 2 * HID, pPart, b2, 1.5f * c3, out);
}